// round 1
// baseline (speedup 1.0000x reference)
#include <cuda_runtime.h>
#include <cstddef>

#define N_NODES 20000
#define N_EDGES 320000
#define F1 1152
#define F2 576
#define F3 288

// ---------------- scratch (device globals; allocation-free) ----------------
__device__ float g_bufA[N_NODES * F1];
__device__ float g_bufB[N_NODES * F1];
__device__ float g_bufC[N_NODES * F1];
__device__ float g_acc1[N_NODES * F1];
__device__ float g_acc2[N_NODES * F2];

__device__ int   g_deg[N_NODES];
__device__ int   g_fill[N_NODES];
__device__ int   g_rowptr[N_NODES + 1];
__device__ int   g_colS[N_EDGES];
__device__ float g_dis[N_NODES];

// ---------------- graph setup ----------------
__global__ void zero_counts_kernel() {
    int i = blockIdx.x * blockDim.x + threadIdx.x;
    if (i < N_NODES) { g_deg[i] = 0; g_fill[i] = 0; }
}

__global__ void hist_kernel(const int* __restrict__ row, const int* __restrict__ col) {
    int e = blockIdx.x * blockDim.x + threadIdx.x;
    if (e < N_EDGES) {
        int r = row[e];
        if (r != col[e]) atomicAdd(&g_deg[r], 1);
    }
}

__global__ void scan_kernel() {
    __shared__ int sums[1024];
    int t = threadIdx.x;
    const int CHUNK = (N_NODES + 1023) / 1024;
    int lo = t * CHUNK;
    int hi = lo + CHUNK; if (hi > N_NODES) hi = N_NODES;
    int s = 0;
    for (int i = lo; i < hi; i++) s += g_deg[i];
    sums[t] = s;
    __syncthreads();
    // Hillis-Steele inclusive scan
    for (int off = 1; off < 1024; off <<= 1) {
        int v = (t >= off) ? sums[t - off] : 0;
        __syncthreads();
        sums[t] += v;
        __syncthreads();
    }
    int run = (t == 0) ? 0 : sums[t - 1];
    for (int i = lo; i < hi; i++) { g_rowptr[i] = run; run += g_deg[i]; }
    if (t == 1023) g_rowptr[N_NODES] = sums[1023];
}

__global__ void dis_kernel() {
    int i = blockIdx.x * blockDim.x + threadIdx.x;
    if (i < N_NODES) {
        int d = g_deg[i];
        g_dis[i] = (d > 0) ? rsqrtf((float)d) : 0.0f;
    }
}

__global__ void scatter_kernel(const int* __restrict__ row, const int* __restrict__ col) {
    int e = blockIdx.x * blockDim.x + threadIdx.x;
    if (e < N_EDGES) {
        int r = row[e], c = col[e];
        if (r != c) {
            int pos = g_rowptr[r] + atomicAdd(&g_fill[r], 1);
            g_colS[pos] = c;
        }
    }
}

// ---------------- propagation: out = alpha * (L~ t) - sub ----------------
// L~ t at row i = -dis[i] * sum_{e in row i} dis[col_e] * t[col_e]
template <int F>
__global__ void prop_kernel(const float* __restrict__ t,
                            const float* __restrict__ sub,
                            float* __restrict__ out,
                            float alpha) {
    constexpr int F4 = F / 4;
    constexpr int NF = (F4 + 127) / 128;
    int i = blockIdx.x;
    int tid = threadIdx.x;
    int s0 = g_rowptr[i], s1 = g_rowptr[i + 1];

    float ax[NF], ay[NF], az[NF], aw[NF];
#pragma unroll
    for (int j = 0; j < NF; j++) { ax[j] = 0.f; ay[j] = 0.f; az[j] = 0.f; aw[j] = 0.f; }

    for (int e = s0; e < s1; e++) {
        int c = g_colS[e];
        float s = g_dis[c];
        const float4* tr = reinterpret_cast<const float4*>(t) + (size_t)c * F4;
#pragma unroll
        for (int j = 0; j < NF; j++) {
            int f = tid + j * 128;
            if ((F4 % 128 == 0) || f < F4) {
                float4 v = tr[f];
                ax[j] += s * v.x; ay[j] += s * v.y;
                az[j] += s * v.z; aw[j] += s * v.w;
            }
        }
    }
    float sc = -alpha * g_dis[i];
    float4* orow = reinterpret_cast<float4*>(out) + (size_t)i * F4;
    const float4* srow = sub ? (reinterpret_cast<const float4*>(sub) + (size_t)i * F4) : nullptr;
#pragma unroll
    for (int j = 0; j < NF; j++) {
        int f = tid + j * 128;
        if ((F4 % 128 == 0) || f < F4) {
            float4 r;
            r.x = sc * ax[j]; r.y = sc * ay[j]; r.z = sc * az[j]; r.w = sc * aw[j];
            if (srow) {
                float4 sv = srow[f];
                r.x -= sv.x; r.y -= sv.y; r.z -= sv.z; r.w -= sv.w;
            }
            orow[f] = r;
        }
    }
}

// ---------------- GEMM: C (+)= A[MxK] @ B[KxN]  (+ bias on init) ----------------
__global__ __launch_bounds__(256)
void gemm_kernel(const float* __restrict__ A, const float* __restrict__ B,
                 const float* __restrict__ bias, float* __restrict__ C,
                 int M, int N, int K, int initMode) {
    constexpr int BM = 128, BN = 128, BK = 8, TM = 8, TN = 8;
    __shared__ float As[BK][BM];
    __shared__ float Bs[BK][BN];
    int tid = threadIdx.x;
    int bm = blockIdx.y * BM, bn = blockIdx.x * BN;

    int arow = tid >> 1;            // 0..127
    int acol = (tid & 1) * 4;       // 0 or 4
    int brow = tid >> 5;            // 0..7
    int bcol = (tid & 31) * 4;      // 0..124

    int tr = (tid >> 4) * TM;
    int tc = (tid & 15) * TN;

    float acc[TM][TN];
#pragma unroll
    for (int i = 0; i < TM; i++)
#pragma unroll
        for (int j = 0; j < TN; j++) acc[i][j] = 0.f;

    bool aval = (bm + arow) < M;
    bool bval = (bn + bcol) < N;
    const float* Aptr = A + (size_t)(bm + arow) * K + acol;

    for (int k0 = 0; k0 < K; k0 += BK) {
        float4 av = aval ? *reinterpret_cast<const float4*>(Aptr + k0)
                         : make_float4(0.f, 0.f, 0.f, 0.f);
        As[acol + 0][arow] = av.x;
        As[acol + 1][arow] = av.y;
        As[acol + 2][arow] = av.z;
        As[acol + 3][arow] = av.w;
        float4 bv = bval ? *reinterpret_cast<const float4*>(B + (size_t)(k0 + brow) * N + bn + bcol)
                         : make_float4(0.f, 0.f, 0.f, 0.f);
        *reinterpret_cast<float4*>(&Bs[brow][bcol]) = bv;
        __syncthreads();
#pragma unroll
        for (int kk = 0; kk < BK; kk++) {
            float ar[TM], br[TN];
            *reinterpret_cast<float4*>(&ar[0]) = *reinterpret_cast<const float4*>(&As[kk][tr]);
            *reinterpret_cast<float4*>(&ar[4]) = *reinterpret_cast<const float4*>(&As[kk][tr + 4]);
            *reinterpret_cast<float4*>(&br[0]) = *reinterpret_cast<const float4*>(&Bs[kk][tc]);
            *reinterpret_cast<float4*>(&br[4]) = *reinterpret_cast<const float4*>(&Bs[kk][tc + 4]);
#pragma unroll
            for (int i = 0; i < TM; i++)
#pragma unroll
                for (int j = 0; j < TN; j++) acc[i][j] += ar[i] * br[j];
        }
        __syncthreads();
    }

#pragma unroll
    for (int i = 0; i < TM; i++) {
        int r = bm + tr + i;
        if (r >= M) continue;
#pragma unroll
        for (int j = 0; j < TN; j++) {
            int cidx = bn + tc + j;
            if (cidx >= N) continue;
            size_t off = (size_t)r * N + cidx;
            float v = acc[i][j];
            v += initMode ? bias[cidx] : C[off];
            C[off] = v;
        }
    }
}

__global__ void relu_kernel(float* __restrict__ p, int n) {
    int i = blockIdx.x * blockDim.x + threadIdx.x;
    if (i < n) {
        float v = p[i];
        p[i] = v > 0.f ? v : 0.f;
    }
}

// ---------------- host orchestration ----------------
static void launch_gemm(const float* A, const float* B, const float* bias,
                        float* C, int M, int N, int K, int initMode) {
    dim3 grid((N + 127) / 128, (M + 127) / 128);
    gemm_kernel<<<grid, 256>>>(A, B, bias, C, M, N, K, initMode);
}

extern "C" void kernel_launch(void* const* d_in, const int* in_sizes, int n_in,
                              void* d_out, int out_size) {
    const float* x   = (const float*)d_in[0];
    const int*   row = (const int*)d_in[1];
    const int*   col = (const int*)d_in[2];
    const float* W1  = (const float*)d_in[3];
    const float* b1  = (const float*)d_in[4];
    const float* W2  = (const float*)d_in[5];
    const float* b2  = (const float*)d_in[6];
    const float* W3  = (const float*)d_in[7];
    const float* b3  = (const float*)d_in[8];
    float* out = (float*)d_out;

    float *bufA, *bufB, *bufC, *acc1, *acc2;
    cudaGetSymbolAddress((void**)&bufA, g_bufA);
    cudaGetSymbolAddress((void**)&bufB, g_bufB);
    cudaGetSymbolAddress((void**)&bufC, g_bufC);
    cudaGetSymbolAddress((void**)&acc1, g_acc1);
    cudaGetSymbolAddress((void**)&acc2, g_acc2);

    const int M = N_NODES;

    // ---- graph setup: degrees, CSR, dis ----
    zero_counts_kernel<<<(N_NODES + 255) / 256, 256>>>();
    hist_kernel<<<(N_EDGES + 255) / 256, 256>>>(row, col);
    scan_kernel<<<1, 1024>>>();
    dis_kernel<<<(N_NODES + 255) / 256, 256>>>();
    scatter_kernel<<<(N_EDGES + 255) / 256, 256>>>(row, col);

    // ================= Layer 1: F=1152 -> 1152, K=6 =================
    {
        const int Fin = F1, Fout = F1;
        const size_t WS = (size_t)Fin * Fout;
        launch_gemm(x, W1 + 0 * WS, b1, acc1, M, Fout, Fin, 1);          // Tx0 = x
        prop_kernel<F1><<<M, 128>>>(x, nullptr, bufA, 1.0f);             // Tx1
        launch_gemm(bufA, W1 + 1 * WS, b1, acc1, M, Fout, Fin, 0);
        prop_kernel<F1><<<M, 128>>>(bufA, x, bufB, 2.0f);                // Tx2
        launch_gemm(bufB, W1 + 2 * WS, b1, acc1, M, Fout, Fin, 0);
        prop_kernel<F1><<<M, 128>>>(bufB, bufA, bufC, 2.0f);             // Tx3
        launch_gemm(bufC, W1 + 3 * WS, b1, acc1, M, Fout, Fin, 0);
        prop_kernel<F1><<<M, 128>>>(bufC, bufB, bufA, 2.0f);             // Tx4
        launch_gemm(bufA, W1 + 4 * WS, b1, acc1, M, Fout, Fin, 0);
        prop_kernel<F1><<<M, 128>>>(bufA, bufC, bufB, 2.0f);             // Tx5
        launch_gemm(bufB, W1 + 5 * WS, b1, acc1, M, Fout, Fin, 0);
        relu_kernel<<<(M * F1 + 255) / 256, 256>>>(acc1, M * F1);
    }

    // ================= Layer 2: F=1152 -> 576, K=5 =================
    {
        const int Fin = F1, Fout = F2;
        const size_t WS = (size_t)Fin * Fout;
        launch_gemm(acc1, W2 + 0 * WS, b2, acc2, M, Fout, Fin, 1);       // Tx0 = h1
        prop_kernel<F1><<<M, 128>>>(acc1, nullptr, bufA, 1.0f);          // Tx1
        launch_gemm(bufA, W2 + 1 * WS, b2, acc2, M, Fout, Fin, 0);
        prop_kernel<F1><<<M, 128>>>(bufA, acc1, bufB, 2.0f);             // Tx2
        launch_gemm(bufB, W2 + 2 * WS, b2, acc2, M, Fout, Fin, 0);
        prop_kernel<F1><<<M, 128>>>(bufB, bufA, bufC, 2.0f);             // Tx3
        launch_gemm(bufC, W2 + 3 * WS, b2, acc2, M, Fout, Fin, 0);
        prop_kernel<F1><<<M, 128>>>(bufC, bufB, bufA, 2.0f);             // Tx4
        launch_gemm(bufA, W2 + 4 * WS, b2, acc2, M, Fout, Fin, 0);
        relu_kernel<<<(M * F2 + 255) / 256, 256>>>(acc2, M * F2);
    }

    // ================= Layer 3: F=576 -> 288, K=5 =================
    {
        const int Fin = F2, Fout = F3;
        const size_t WS = (size_t)Fin * Fout;
        launch_gemm(acc2, W3 + 0 * WS, b3, out, M, Fout, Fin, 1);        // Tx0 = h2
        prop_kernel<F2><<<M, 128>>>(acc2, nullptr, bufA, 1.0f);          // Tx1
        launch_gemm(bufA, W3 + 1 * WS, b3, out, M, Fout, Fin, 0);
        prop_kernel<F2><<<M, 128>>>(bufA, acc2, bufB, 2.0f);             // Tx2
        launch_gemm(bufB, W3 + 2 * WS, b3, out, M, Fout, Fin, 0);
        prop_kernel<F2><<<M, 128>>>(bufB, bufA, bufC, 2.0f);             // Tx3
        launch_gemm(bufC, W3 + 3 * WS, b3, out, M, Fout, Fin, 0);
        prop_kernel<F2><<<M, 128>>>(bufC, bufB, bufA, 2.0f);             // Tx4
        launch_gemm(bufA, W3 + 4 * WS, b3, out, M, Fout, Fin, 0);
        relu_kernel<<<(M * F3 + 255) / 256, 256>>>(out, M * F3);
    }
}

// round 3
// speedup vs baseline: 1.9297x; 1.9297x over previous
#include <cuda_runtime.h>
#include <cuda_bf16.h>
#include <cstdint>
#include <cstddef>

#define N_NODES 20000
#define N_EDGES 320000
#define M_PAD   20096          // 157 * 128
#define F1 1152
#define F2 576
#define F3 288

#define KCAT1 (6 * F1)         // 6912
#define KCAT2 (5 * F1)         // 5760
#define KCAT3 (5 * F2)         // 2880
#define N1PAD 1152             // 9 * 128
#define N2PAD 640              // 5 * 128
#define N3PAD 384              // 3 * 128

// ---------------- scratch (device globals; allocation-free) ----------------
__device__ float g_bufA[N_NODES * F1];
__device__ float g_bufB[N_NODES * F1];
__device__ float g_bufC[N_NODES * F1];
__device__ float g_acc1[N_NODES * F1];
__device__ float g_acc2[N_NODES * F2];

__device__ __nv_bfloat16 g_Ahi[(size_t)M_PAD * KCAT1];
__device__ __nv_bfloat16 g_Alo[(size_t)M_PAD * KCAT1];
__device__ __nv_bfloat16 g_W1h[(size_t)N1PAD * KCAT1];
__device__ __nv_bfloat16 g_W1l[(size_t)N1PAD * KCAT1];
__device__ __nv_bfloat16 g_W2h[(size_t)N2PAD * KCAT2];
__device__ __nv_bfloat16 g_W2l[(size_t)N2PAD * KCAT2];
__device__ __nv_bfloat16 g_W3h[(size_t)N3PAD * KCAT3];
__device__ __nv_bfloat16 g_W3l[(size_t)N3PAD * KCAT3];

__device__ int   g_deg[N_NODES];
__device__ int   g_fill[N_NODES];
__device__ int   g_rowptr[N_NODES + 1];
__device__ int   g_colS[N_EDGES];
__device__ float g_dis[N_NODES];

// ---------------- PTX helpers (base sm_103 target only) ----------------
__device__ __forceinline__ uint32_t smem_u32(const void* p) {
    uint32_t a;
    asm("{ .reg .u64 t; cvta.to.shared.u64 t, %1; cvt.u32.u64 %0, t; }" : "=r"(a) : "l"(p));
    return a;
}

#define CP_ASYNC16(dst, src) \
    asm volatile("cp.async.cg.shared.global [%0], [%1], 16;" :: "r"(dst), "l"(src) : "memory")
#define CP_COMMIT() asm volatile("cp.async.commit_group;" ::: "memory")
#define CP_WAIT2()  asm volatile("cp.async.wait_group 2;" ::: "memory")

#define LDMATRIX_X4(r0, r1, r2, r3, addr) \
    asm volatile("ldmatrix.sync.aligned.m8n8.x4.shared.b16 {%0,%1,%2,%3}, [%4];" \
                 : "=r"(r0), "=r"(r1), "=r"(r2), "=r"(r3) : "r"(addr))

#define MMA_BF16(d, a, b) \
    asm volatile("mma.sync.aligned.m16n8k16.row.col.f32.bf16.bf16.f32 " \
                 "{%0,%1,%2,%3}, {%4,%5,%6,%7}, {%8,%9}, {%0,%1,%2,%3};" \
                 : "+f"((d)[0]), "+f"((d)[1]), "+f"((d)[2]), "+f"((d)[3]) \
                 : "r"((a)[0]), "r"((a)[1]), "r"((a)[2]), "r"((a)[3]), \
                   "r"((b)[0]), "r"((b)[1]))

// ---------------- graph setup ----------------
__global__ void zero_counts_kernel() {
    int i = blockIdx.x * blockDim.x + threadIdx.x;
    if (i < N_NODES) { g_deg[i] = 0; g_fill[i] = 0; }
}
__global__ void hist_kernel(const int* __restrict__ row, const int* __restrict__ col) {
    int e = blockIdx.x * blockDim.x + threadIdx.x;
    if (e < N_EDGES) {
        int r = row[e];
        if (r != col[e]) atomicAdd(&g_deg[r], 1);
    }
}
__global__ void scan_kernel() {
    __shared__ int sums[1024];
    int t = threadIdx.x;
    const int CHUNK = (N_NODES + 1023) / 1024;
    int lo = t * CHUNK, hi = lo + CHUNK;
    if (hi > N_NODES) hi = N_NODES;
    int s = 0;
    for (int i = lo; i < hi; i++) s += g_deg[i];
    sums[t] = s;
    __syncthreads();
    for (int off = 1; off < 1024; off <<= 1) {
        int v = (t >= off) ? sums[t - off] : 0;
        __syncthreads();
        sums[t] += v;
        __syncthreads();
    }
    int run = (t == 0) ? 0 : sums[t - 1];
    for (int i = lo; i < hi; i++) { g_rowptr[i] = run; run += g_deg[i]; }
    if (t == 1023) g_rowptr[N_NODES] = sums[1023];
}
__global__ void dis_kernel() {
    int i = blockIdx.x * blockDim.x + threadIdx.x;
    if (i < N_NODES) {
        int d = g_deg[i];
        g_dis[i] = (d > 0) ? rsqrtf((float)d) : 0.0f;
    }
}
__global__ void scatter_kernel(const int* __restrict__ row, const int* __restrict__ col) {
    int e = blockIdx.x * blockDim.x + threadIdx.x;
    if (e < N_EDGES) {
        int r = row[e], c = col[e];
        if (r != c) {
            int pos = g_rowptr[r] + atomicAdd(&g_fill[r], 1);
            g_colS[pos] = c;
        }
    }
}

// ---------------- split helpers ----------------
__device__ __forceinline__ void split1(float v, __nv_bfloat16& h, __nv_bfloat16& l) {
    h = __float2bfloat16(v);
    l = __float2bfloat16(v - __bfloat162float(h));
}

// convert Tx0 (fp32 [M x F]) into cat slice; zero pad rows
__global__ void convert_split_kernel(const float* __restrict__ src, int F,
                                     __nv_bfloat16* __restrict__ hi,
                                     __nv_bfloat16* __restrict__ lo,
                                     int ldCat, int colOff) {
    int total = M_PAD * F;
    for (int idx = blockIdx.x * blockDim.x + threadIdx.x; idx < total;
         idx += gridDim.x * blockDim.x) {
        int r = idx / F, c = idx - r * F;
        float v = (r < N_NODES) ? src[(size_t)r * F + c] : 0.0f;
        __nv_bfloat16 h, l;
        split1(v, h, l);
        size_t o = (size_t)r * ldCat + colOff + c;
        hi[o] = h; lo[o] = l;
    }
}

// weight transpose + split: W [Kcat x N] fp32 -> WT hi/lo [Npad x Kcat] bf16
__global__ void wsplit_kernel(const float* __restrict__ W, int Kcat, int N, int Npad,
                              __nv_bfloat16* __restrict__ hi,
                              __nv_bfloat16* __restrict__ lo) {
    __shared__ float tile[32][33];
    int k0 = blockIdx.x * 32, n0 = blockIdx.y * 32;
    int tx = threadIdx.x, ty = threadIdx.y;   // (32, 8)
#pragma unroll
    for (int r = 0; r < 32; r += 8) {
        int kk = k0 + ty + r, nn = n0 + tx;
        tile[ty + r][tx] = (kk < Kcat && nn < N) ? W[(size_t)kk * N + nn] : 0.0f;
    }
    __syncthreads();
#pragma unroll
    for (int r = 0; r < 32; r += 8) {
        int nn = n0 + ty + r, kk = k0 + tx;
        if (nn < Npad && kk < Kcat) {
            float v = tile[tx][ty + r];
            __nv_bfloat16 h, l;
            split1(v, h, l);
            hi[(size_t)nn * Kcat + kk] = h;
            lo[(size_t)nn * Kcat + kk] = l;
        }
    }
}

// ---------------- propagation with fused bf16 split of the output ----------
// out = alpha * (L~ t) - sub ; also writes hi/lo split into cat slice.
template <int F>
__global__ void prop_kernel(const float* __restrict__ t,
                            const float* __restrict__ sub,
                            float* __restrict__ out,
                            __nv_bfloat16* __restrict__ hi,
                            __nv_bfloat16* __restrict__ lo,
                            int ldCat, int colOff, float alpha) {
    constexpr int F4 = F / 4;
    constexpr int NF = (F4 + 127) / 128;
    int i = blockIdx.x;
    int tid = threadIdx.x;
    bool real = (i < N_NODES);
    int s0 = real ? g_rowptr[i] : 0;
    int s1 = real ? g_rowptr[i + 1] : 0;

    float ax[NF], ay[NF], az[NF], aw[NF];
#pragma unroll
    for (int j = 0; j < NF; j++) { ax[j] = 0.f; ay[j] = 0.f; az[j] = 0.f; aw[j] = 0.f; }

    for (int e = s0; e < s1; e++) {
        int c = g_colS[e];
        float s = g_dis[c];
        const float4* tr = reinterpret_cast<const float4*>(t) + (size_t)c * F4;
#pragma unroll
        for (int j = 0; j < NF; j++) {
            int f = tid + j * 128;
            if ((F4 % 128 == 0) || f < F4) {
                float4 v = tr[f];
                ax[j] += s * v.x; ay[j] += s * v.y;
                az[j] += s * v.z; aw[j] += s * v.w;
            }
        }
    }
    float sc = real ? (-alpha * g_dis[i]) : 0.0f;
    float4* orow = real ? (reinterpret_cast<float4*>(out) + (size_t)i * F4) : nullptr;
    const float4* srow = (real && sub)
        ? (reinterpret_cast<const float4*>(sub) + (size_t)i * F4) : nullptr;
#pragma unroll
    for (int j = 0; j < NF; j++) {
        int f = tid + j * 128;
        if ((F4 % 128 == 0) || f < F4) {
            float4 r;
            r.x = sc * ax[j]; r.y = sc * ay[j]; r.z = sc * az[j]; r.w = sc * aw[j];
            if (srow) {
                float4 sv = srow[f];
                r.x -= sv.x; r.y -= sv.y; r.z -= sv.z; r.w -= sv.w;
            }
            if (orow) orow[f] = r;
            __nv_bfloat16 hx, lx, hy, ly, hz, lz, hw, lw;
            split1(r.x, hx, lx); split1(r.y, hy, ly);
            split1(r.z, hz, lz); split1(r.w, hw, lw);
            size_t o = (size_t)i * ldCat + colOff + (size_t)f * 4;
            __nv_bfloat162* hp = reinterpret_cast<__nv_bfloat162*>(hi + o);
            __nv_bfloat162* lp = reinterpret_cast<__nv_bfloat162*>(lo + o);
            hp[0] = __nv_bfloat162(hx, hy); hp[1] = __nv_bfloat162(hz, hw);
            lp[0] = __nv_bfloat162(lx, ly); lp[1] = __nv_bfloat162(lz, lw);
        }
    }
}

// ---------------- mma.sync GEMM ----------------
// C[M x N] = relu( A x B^T + bias ) where the product is a 3-pass bf16 split
// (Ahi*Bhi + Alo*Bhi + Ahi*Blo) expressed as one long K loop.
// A: [M_PAD x Kcat] bf16 row-major.  B: [Npad x Kcat] bf16 row-major (= W^T).
// CTA tile 128x128, BK=32, 4-stage cp.async pipeline, 8 warps of 64x32.
#define GSTAGES 4
#define GBK     32
#define ROWB    80                    // padded SMEM row bytes (40 bf16)
#define ATILE_B (128 * ROWB)          // 10240
#define STG_B   (2 * ATILE_B)         // 20480 per stage (A then B)
#define SMEM_TOTAL_GEMM (GSTAGES * STG_B)   // 81920

__global__ void __launch_bounds__(256, 2)
gemm_mma_kernel(const __nv_bfloat16* __restrict__ Ahi, const __nv_bfloat16* __restrict__ Alo,
                const __nv_bfloat16* __restrict__ Bhi, const __nv_bfloat16* __restrict__ Blo,
                const float* __restrict__ bias, float* __restrict__ C,
                int N, int Kcat) {
    extern __shared__ char smem[];
    uint32_t sb = smem_u32(smem);
    int tid = threadIdx.x;
    int lane = tid & 31;
    int wid = tid >> 5;
    int bm = blockIdx.y * 128;
    int bn = blockIdx.x * 128;

    const int kt = Kcat / GBK;         // k-tiles per pass
    const int NIT = 3 * kt;

    int wm = (wid & 1) * 64;           // warp M offset in tile
    int wn = (wid >> 1) * 32;          // warp N offset in tile

    float d[4][4][4];
#pragma unroll
    for (int i = 0; i < 4; i++)
#pragma unroll
        for (int j = 0; j < 4; j++)
#pragma unroll
            for (int q = 0; q < 4; q++) d[i][j][q] = 0.f;

    // per-thread load coords (2 chunks of 16B for A, 2 for B, per stage)
    int r0 = tid >> 2,          p0 = tid & 3;
    int r1 = (tid + 256) >> 2,  p1 = (tid + 256) & 3;

    auto issue = [&](int it) {
        int pass = it / kt;
        int kk = (it - pass * kt) * GBK;
        const __nv_bfloat16* Ab = (pass == 1) ? Alo : Ahi;
        const __nv_bfloat16* Bb = (pass == 2) ? Blo : Bhi;
        int s = it & (GSTAGES - 1);
        uint32_t sA = sb + s * STG_B;
        uint32_t sB = sA + ATILE_B;
        const char* gA = (const char*)(Ab + (size_t)bm * Kcat + kk);
        const char* gB = (const char*)(Bb + (size_t)bn * Kcat + kk);
        size_t ld = (size_t)Kcat * 2;
        CP_ASYNC16(sA + r0 * ROWB + p0 * 16, gA + (size_t)r0 * ld + p0 * 16);
        CP_ASYNC16(sA + r1 * ROWB + p1 * 16, gA + (size_t)r1 * ld + p1 * 16);
        CP_ASYNC16(sB + r0 * ROWB + p0 * 16, gB + (size_t)r0 * ld + p0 * 16);
        CP_ASYNC16(sB + r1 * ROWB + p1 * 16, gB + (size_t)r1 * ld + p1 * 16);
    };

    // prologue: fill 3 stages
#pragma unroll
    for (int it = 0; it < GSTAGES - 1; it++) { issue(it); CP_COMMIT(); }

    int lrow = lane & 15;              // ldmatrix row within 16
    int lcol = (lane >> 4) * 8;        // ldmatrix k-half select

    for (int it = 0; it < NIT; ++it) {
        CP_WAIT2();
        __syncthreads();

        int s = it & (GSTAGES - 1);
        uint32_t sA = sb + s * STG_B;
        uint32_t sB = sA + ATILE_B;

#pragma unroll
        for (int ks = 0; ks < GBK; ks += 16) {
            uint32_t a[4][4], b[4][2];
#pragma unroll
            for (int i = 0; i < 4; i++) {
                uint32_t addr = sA + (wm + i * 16 + lrow) * ROWB + (ks + lcol) * 2;
                LDMATRIX_X4(a[i][0], a[i][1], a[i][2], a[i][3], addr);
            }
#pragma unroll
            for (int jp = 0; jp < 2; jp++) {
                uint32_t q0, q1, q2, q3;
                uint32_t addr = sB + (wn + jp * 16 + lrow) * ROWB + (ks + lcol) * 2;
                LDMATRIX_X4(q0, q1, q2, q3, addr);
                b[2 * jp][0] = q0; b[2 * jp][1] = q2;
                b[2 * jp + 1][0] = q1; b[2 * jp + 1][1] = q3;
            }
#pragma unroll
            for (int i = 0; i < 4; i++)
#pragma unroll
                for (int j = 0; j < 4; j++)
                    MMA_BF16(d[i][j], a[i], b[j]);
        }

        __syncthreads();
        if (it + GSTAGES - 1 < NIT) issue(it + GSTAGES - 1);
        CP_COMMIT();
    }

    // epilogue: bias + relu, fp32 writes
    int gr = lane >> 2;
    int gc = (lane & 3) * 2;
#pragma unroll
    for (int i = 0; i < 4; i++) {
#pragma unroll
        for (int j = 0; j < 4; j++) {
            int colb = bn + wn + j * 8 + gc;
            if (colb >= N) continue;
            float b0 = bias[colb], b1 = bias[colb + 1];
            int row0 = bm + wm + i * 16 + gr;
            if (row0 < N_NODES) {
                float2 v;
                v.x = fmaxf(d[i][j][0] + b0, 0.f);
                v.y = fmaxf(d[i][j][1] + b1, 0.f);
                *reinterpret_cast<float2*>(&C[(size_t)row0 * N + colb]) = v;
            }
            int row1 = row0 + 8;
            if (row1 < N_NODES) {
                float2 v;
                v.x = fmaxf(d[i][j][2] + b0, 0.f);
                v.y = fmaxf(d[i][j][3] + b1, 0.f);
                *reinterpret_cast<float2*>(&C[(size_t)row1 * N + colb]) = v;
            }
        }
    }
}

// ---------------- host orchestration ----------------
extern "C" void kernel_launch(void* const* d_in, const int* in_sizes, int n_in,
                              void* d_out, int out_size) {
    const float* x   = (const float*)d_in[0];
    const int*   row = (const int*)d_in[1];
    const int*   col = (const int*)d_in[2];
    const float* W1  = (const float*)d_in[3];
    const float* b1  = (const float*)d_in[4];
    const float* W2  = (const float*)d_in[5];
    const float* b2  = (const float*)d_in[6];
    const float* W3  = (const float*)d_in[7];
    const float* b3  = (const float*)d_in[8];
    float* out = (float*)d_out;

    float *bufA, *bufB, *bufC, *acc1, *acc2;
    __nv_bfloat16 *Ahi, *Alo, *W1h, *W1l, *W2h, *W2l, *W3h, *W3l;
    cudaGetSymbolAddress((void**)&bufA, g_bufA);
    cudaGetSymbolAddress((void**)&bufB, g_bufB);
    cudaGetSymbolAddress((void**)&bufC, g_bufC);
    cudaGetSymbolAddress((void**)&acc1, g_acc1);
    cudaGetSymbolAddress((void**)&acc2, g_acc2);
    cudaGetSymbolAddress((void**)&Ahi, g_Ahi);
    cudaGetSymbolAddress((void**)&Alo, g_Alo);
    cudaGetSymbolAddress((void**)&W1h, g_W1h);
    cudaGetSymbolAddress((void**)&W1l, g_W1l);
    cudaGetSymbolAddress((void**)&W2h, g_W2h);
    cudaGetSymbolAddress((void**)&W2l, g_W2l);
    cudaGetSymbolAddress((void**)&W3h, g_W3h);
    cudaGetSymbolAddress((void**)&W3l, g_W3l);

    cudaFuncSetAttribute(gemm_mma_kernel,
                         cudaFuncAttributeMaxDynamicSharedMemorySize, SMEM_TOTAL_GEMM);

    // ---- graph setup ----
    zero_counts_kernel<<<(N_NODES + 255) / 256, 256>>>();
    hist_kernel<<<(N_EDGES + 255) / 256, 256>>>(row, col);
    scan_kernel<<<1, 1024>>>();
    dis_kernel<<<(N_NODES + 255) / 256, 256>>>();
    scatter_kernel<<<(N_EDGES + 255) / 256, 256>>>(row, col);

    // ---- weight conversions ----
    {
        dim3 g1((KCAT1 + 31) / 32, (N1PAD + 31) / 32);
        wsplit_kernel<<<g1, dim3(32, 8)>>>(W1, KCAT1, F1, N1PAD, W1h, W1l);
        dim3 g2((KCAT2 + 31) / 32, (N2PAD + 31) / 32);
        wsplit_kernel<<<g2, dim3(32, 8)>>>(W2, KCAT2, F2, N2PAD, W2h, W2l);
        dim3 g3((KCAT3 + 31) / 32, (N3PAD + 31) / 32);
        wsplit_kernel<<<g3, dim3(32, 8)>>>(W3, KCAT3, F3, N3PAD, W3h, W3l);
    }

    // ================= Layer 1: 1152 -> 1152, K=6, Kcat=6912 =================
    convert_split_kernel<<<4096, 256>>>(x, F1, Ahi, Alo, KCAT1, 0);
    prop_kernel<F1><<<M_PAD, 128>>>(x,    nullptr, bufA, Ahi, Alo, KCAT1, 1 * F1, 1.0f);
    prop_kernel<F1><<<M_PAD, 128>>>(bufA, x,       bufB, Ahi, Alo, KCAT1, 2 * F1, 2.0f);
    prop_kernel<F1><<<M_PAD, 128>>>(bufB, bufA,    bufC, Ahi, Alo, KCAT1, 3 * F1, 2.0f);
    prop_kernel<F1><<<M_PAD, 128>>>(bufC, bufB,    bufA, Ahi, Alo, KCAT1, 4 * F1, 2.0f);
    prop_kernel<F1><<<M_PAD, 128>>>(bufA, bufC,    bufB, Ahi, Alo, KCAT1, 5 * F1, 2.0f);
    {
        dim3 grid(N1PAD / 128, M_PAD / 128);
        gemm_mma_kernel<<<grid, 256, SMEM_TOTAL_GEMM>>>(Ahi, Alo, W1h, W1l, b1, acc1, F1, KCAT1);
    }

    // ================= Layer 2: 1152 -> 576, K=5, Kcat=5760 =================
    convert_split_kernel<<<4096, 256>>>(acc1, F1, Ahi, Alo, KCAT2, 0);
    prop_kernel<F1><<<M_PAD, 128>>>(acc1, nullptr, bufA, Ahi, Alo, KCAT2, 1 * F1, 1.0f);
    prop_kernel<F1><<<M_PAD, 128>>>(bufA, acc1,    bufB, Ahi, Alo, KCAT2, 2 * F1, 2.0f);
    prop_kernel<F1><<<M_PAD, 128>>>(bufB, bufA,    bufC, Ahi, Alo, KCAT2, 3 * F1, 2.0f);
    prop_kernel<F1><<<M_PAD, 128>>>(bufC, bufB,    bufA, Ahi, Alo, KCAT2, 4 * F1, 2.0f);
    {
        dim3 grid(N2PAD / 128, M_PAD / 128);
        gemm_mma_kernel<<<grid, 256, SMEM_TOTAL_GEMM>>>(Ahi, Alo, W2h, W2l, b2, acc2, F2, KCAT2);
    }

    // ================= Layer 3: 576 -> 288, K=5, Kcat=2880 =================
    convert_split_kernel<<<4096, 256>>>(acc2, F2, Ahi, Alo, KCAT3, 0);
    prop_kernel<F2><<<M_PAD, 128>>>(acc2, nullptr, bufA, Ahi, Alo, KCAT3, 1 * F2, 1.0f);
    prop_kernel<F2><<<M_PAD, 128>>>(bufA, acc2,    bufB, Ahi, Alo, KCAT3, 2 * F2, 2.0f);
    prop_kernel<F2><<<M_PAD, 128>>>(bufB, bufA,    bufC, Ahi, Alo, KCAT3, 3 * F2, 2.0f);
    prop_kernel<F2><<<M_PAD, 128>>>(bufC, bufB,    bufA, Ahi, Alo, KCAT3, 4 * F2, 2.0f);
    {
        dim3 grid(N3PAD / 128, M_PAD / 128);
        gemm_mma_kernel<<<grid, 256, SMEM_TOTAL_GEMM>>>(Ahi, Alo, W3h, W3l, b3, out, F3, KCAT3);
    }
}